// round 1
// baseline (speedup 1.0000x reference)
#include <cuda_runtime.h>
#include <math.h>
#include <stdint.h>

#define B_ 4
#define T_ 1024
#define C_ 1024
#define H_ 16
#define HS_ 64
#define L_ 12
#define V_ 50304
#define M_ 4096  // B*T

static const size_t NLOGITS = (size_t)M_ * V_;  // 206045184

// ---------------- scratch (device globals; no allocs allowed) ----------------
__device__ float g_x[(size_t)M_ * C_];
__device__ float g_h[(size_t)M_ * C_];
__device__ float g_q[(size_t)M_ * C_];
__device__ float g_k[(size_t)M_ * C_];
__device__ float g_v[(size_t)M_ * C_];
__device__ float g_att[(size_t)M_ * C_];
__device__ float g_mlp[(size_t)M_ * 4 * C_];
__device__ float g_wei[(size_t)B_ * H_ * T_ * T_];
__device__ float g_loss_acc;

// ---------------- embedding: x = tok_emb[idx] + pos_emb[t] ----------------
__global__ void __launch_bounds__(256) embed_kernel(
    const int* __restrict__ idx, const float* __restrict__ tok,
    const float* __restrict__ pos, float* __restrict__ x)
{
    int row = blockIdx.x;          // 0..4095 (b*T + t)
    int t   = row & (T_ - 1);
    int token = idx[row];
    int c = threadIdx.x * 4;
    float4 a = *(const float4*)(tok + (size_t)token * C_ + c);
    float4 p = *(const float4*)(pos + (size_t)t * C_ + c);
    float4 o = make_float4(a.x + p.x, a.y + p.y, a.z + p.z, a.w + p.w);
    *(float4*)(x + (size_t)row * C_ + c) = o;
}

// ---------------- layernorm over C=1024, block per row ----------------
__global__ void __launch_bounds__(256) ln_kernel(
    const float* __restrict__ x, const float* __restrict__ g,
    const float* __restrict__ b, float* __restrict__ y)
{
    __shared__ float red[256];
    int row = blockIdx.x;
    int t = threadIdx.x;
    const float* xr = x + (size_t)row * C_;
    float4 v = *(const float4*)(xr + t * 4);
    red[t] = v.x + v.y + v.z + v.w;
    __syncthreads();
    for (int o = 128; o > 0; o >>= 1) { if (t < o) red[t] += red[t + o]; __syncthreads(); }
    float mean = red[0] * (1.f / C_);
    __syncthreads();
    float dx = v.x - mean, dy = v.y - mean, dz = v.z - mean, dw = v.w - mean;
    red[t] = dx * dx + dy * dy + dz * dz + dw * dw;
    __syncthreads();
    for (int o = 128; o > 0; o >>= 1) { if (t < o) red[t] += red[t + o]; __syncthreads(); }
    float inv = rsqrtf(red[0] * (1.f / C_) + 1e-5f);
    float4 gv = *(const float4*)(g + t * 4);
    float4 bv = *(const float4*)(b + t * 4);
    float4 o4 = make_float4(dx * inv * gv.x + bv.x, dy * inv * gv.y + bv.y,
                            dz * inv * gv.z + bv.z, dw * inv * gv.w + bv.w);
    *(float4*)(y + (size_t)row * C_ + t * 4) = o4;
}

// ---------------- SGEMM: C = A(MxK) @ B(KxN) [+bias] [+res] [relu] ----------------
// BM=128, BN=128, BK=16, 256 threads, 8x8 per thread.
__global__ void __launch_bounds__(256) gemm_kernel(
    const float* __restrict__ A, const float* __restrict__ B,
    const float* __restrict__ bias, const float* __restrict__ res,
    float* __restrict__ C, int M, int N, int K, int relu)
{
    __shared__ float As[16][128];
    __shared__ float Bs[16][128];
    int bm = blockIdx.y * 128;
    int bn = blockIdx.x * 128;
    int tid = threadIdx.x;
    int tx = tid & 15, ty = tid >> 4;

    float acc[8][8];
    #pragma unroll
    for (int i = 0; i < 8; i++)
        #pragma unroll
        for (int j = 0; j < 8; j++) acc[i][j] = 0.f;

    const float* Aptr = A + (size_t)bm * K;
    const float* Bptr = B + bn;

    for (int k0 = 0; k0 < K; k0 += 16) {
        #pragma unroll
        for (int l = tid; l < 512; l += 256) {
            int row = l >> 2, c4 = l & 3;
            float4 v = *(const float4*)(Aptr + (size_t)row * K + k0 + c4 * 4);
            As[c4 * 4 + 0][row] = v.x;
            As[c4 * 4 + 1][row] = v.y;
            As[c4 * 4 + 2][row] = v.z;
            As[c4 * 4 + 3][row] = v.w;
        }
        #pragma unroll
        for (int l = tid; l < 512; l += 256) {
            int row = l >> 5, c4 = l & 31;
            float4 v = *(const float4*)(Bptr + (size_t)(k0 + row) * N + c4 * 4);
            *(float4*)(&Bs[row][c4 * 4]) = v;
        }
        __syncthreads();
        #pragma unroll
        for (int kk = 0; kk < 16; kk++) {
            float a[8], bb[8];
            *(float4*)(a)      = *(const float4*)(&As[kk][ty * 8]);
            *(float4*)(a + 4)  = *(const float4*)(&As[kk][ty * 8 + 4]);
            *(float4*)(bb)     = *(const float4*)(&Bs[kk][tx * 8]);
            *(float4*)(bb + 4) = *(const float4*)(&Bs[kk][tx * 8 + 4]);
            #pragma unroll
            for (int i = 0; i < 8; i++)
                #pragma unroll
                for (int j = 0; j < 8; j++)
                    acc[i][j] = fmaf(a[i], bb[j], acc[i][j]);
        }
        __syncthreads();
    }

    float bvals[8];
    if (bias) {
        *(float4*)(bvals)     = *(const float4*)(bias + bn + tx * 8);
        *(float4*)(bvals + 4) = *(const float4*)(bias + bn + tx * 8 + 4);
    } else {
        #pragma unroll
        for (int j = 0; j < 8; j++) bvals[j] = 0.f;
    }

    #pragma unroll
    for (int i = 0; i < 8; i++) {
        int row = bm + ty * 8 + i;
        float* Crow = C + (size_t)row * N + bn + tx * 8;
        float out[8];
        #pragma unroll
        for (int j = 0; j < 8; j++) out[j] = acc[i][j] + bvals[j];
        if (res) {
            const float* Rrow = res + (size_t)row * N + bn + tx * 8;
            float4 r0 = *(const float4*)(Rrow);
            float4 r1 = *(const float4*)(Rrow + 4);
            out[0] += r0.x; out[1] += r0.y; out[2] += r0.z; out[3] += r0.w;
            out[4] += r1.x; out[5] += r1.y; out[6] += r1.z; out[7] += r1.w;
        }
        if (relu) {
            #pragma unroll
            for (int j = 0; j < 8; j++) out[j] = fmaxf(out[j], 0.f);
        }
        *(float4*)(Crow)     = *(float4*)(out);
        *(float4*)(Crow + 4) = *(float4*)(out + 4);
    }
}

// ---------------- attention scores: wei[bh,q,k] = q . k  (64x64 tiles) ----------------
__global__ void __launch_bounds__(256) attn_scores_kernel(
    const float* __restrict__ q, const float* __restrict__ k, float* __restrict__ wei)
{
    int kt = blockIdx.x << 6;
    int qt = blockIdx.y << 6;
    if (kt > qt) return;                 // fully masked tile
    int bh = blockIdx.z;
    int b = bh >> 4, h = bh & 15;
    __shared__ float Qs[64][68];         // [d][qrow]
    __shared__ float Ks[64][68];         // [d][krow]
    int tid = threadIdx.x;
    const float* qbase = q + ((size_t)(b * T_ + qt)) * C_ + h * HS_;
    const float* kbase = k + ((size_t)(b * T_ + kt)) * C_ + h * HS_;
    #pragma unroll
    for (int l = tid; l < 1024; l += 256) {
        int r = l >> 4, c4 = l & 15;
        float4 v = *(const float4*)(qbase + (size_t)r * C_ + c4 * 4);
        Qs[c4 * 4 + 0][r] = v.x; Qs[c4 * 4 + 1][r] = v.y;
        Qs[c4 * 4 + 2][r] = v.z; Qs[c4 * 4 + 3][r] = v.w;
        float4 w = *(const float4*)(kbase + (size_t)r * C_ + c4 * 4);
        Ks[c4 * 4 + 0][r] = w.x; Ks[c4 * 4 + 1][r] = w.y;
        Ks[c4 * 4 + 2][r] = w.z; Ks[c4 * 4 + 3][r] = w.w;
    }
    __syncthreads();
    int tx = tid & 15, ty = tid >> 4;
    float acc[4][4];
    #pragma unroll
    for (int i = 0; i < 4; i++)
        #pragma unroll
        for (int j = 0; j < 4; j++) acc[i][j] = 0.f;
    #pragma unroll 8
    for (int d = 0; d < 64; d++) {
        float a[4], bb[4];
        *(float4*)a  = *(const float4*)(&Qs[d][ty * 4]);
        *(float4*)bb = *(const float4*)(&Ks[d][tx * 4]);
        #pragma unroll
        for (int i = 0; i < 4; i++)
            #pragma unroll
            for (int j = 0; j < 4; j++)
                acc[i][j] = fmaf(a[i], bb[j], acc[i][j]);
    }
    #pragma unroll
    for (int i = 0; i < 4; i++) {
        size_t roff = ((size_t)bh * T_ + qt + ty * 4 + i) * T_ + kt + tx * 4;
        *(float4*)(wei + roff) = *(float4*)(acc[i]);
    }
}

// ---------------- masked softmax over k (scale 1/8) ----------------
__global__ void __launch_bounds__(256) softmax_kernel(float* __restrict__ wei)
{
    __shared__ float red[256];
    int row = blockIdx.x;                // bh*T + q
    int q = row & (T_ - 1);
    float* w = wei + (size_t)row * T_;
    int kend = ((q >> 6) + 1) << 6;
    int t = threadIdx.x;
    int k0 = t * 4;
    float vals[4];
    float mx = -INFINITY;
    #pragma unroll
    for (int j = 0; j < 4; j++) {
        int kk = k0 + j;
        float v = (kk <= q) ? w[kk] * 0.125f : -INFINITY;
        vals[j] = v;
        mx = fmaxf(mx, v);
    }
    red[t] = mx; __syncthreads();
    for (int o = 128; o > 0; o >>= 1) { if (t < o) red[t] = fmaxf(red[t], red[t + o]); __syncthreads(); }
    float Mx = red[0]; __syncthreads();
    float s = 0.f;
    #pragma unroll
    for (int j = 0; j < 4; j++) {
        int kk = k0 + j;
        float e = (kk <= q) ? __expf(vals[j] - Mx) : 0.f;
        vals[j] = e;
        s += e;
    }
    red[t] = s; __syncthreads();
    for (int o = 128; o > 0; o >>= 1) { if (t < o) red[t] += red[t + o]; __syncthreads(); }
    float invS = 1.f / red[0];
    #pragma unroll
    for (int j = 0; j < 4; j++) {
        int kk = k0 + j;
        if (kk < kend) w[kk] = vals[j] * invS;
    }
}

// ---------------- att = wei @ V, written back to [b,t,h*HS+d] ----------------
__global__ void __launch_bounds__(256) attn_av_kernel(
    const float* __restrict__ wei, const float* __restrict__ v, float* __restrict__ att)
{
    int qt = blockIdx.x << 6;
    int bh = blockIdx.y;
    int b = bh >> 4, h = bh & 15;
    __shared__ float Ws[64][68];   // [qrow][k]
    __shared__ float Vs[64][68];   // [krow][d]
    int tid = threadIdx.x;
    int tx = tid & 15, ty = tid >> 4;
    float acc[4][4];
    #pragma unroll
    for (int i = 0; i < 4; i++)
        #pragma unroll
        for (int j = 0; j < 4; j++) acc[i][j] = 0.f;

    for (int kt = 0; kt <= qt; kt += 64) {
        const float* wbase = wei + ((size_t)bh * T_ + qt) * T_ + kt;
        const float* vbase = v + ((size_t)(b * T_ + kt)) * C_ + h * HS_;
        #pragma unroll
        for (int l = tid; l < 1024; l += 256) {
            int r = l >> 4, c4 = l & 15;
            *(float4*)(&Ws[r][c4 * 4]) = *(const float4*)(wbase + (size_t)r * T_ + c4 * 4);
            *(float4*)(&Vs[r][c4 * 4]) = *(const float4*)(vbase + (size_t)r * C_ + c4 * 4);
        }
        __syncthreads();
        #pragma unroll 8
        for (int kk = 0; kk < 64; kk++) {
            float bb[4];
            *(float4*)bb = *(const float4*)(&Vs[kk][tx * 4]);
            float a0 = Ws[ty * 4 + 0][kk];
            float a1 = Ws[ty * 4 + 1][kk];
            float a2 = Ws[ty * 4 + 2][kk];
            float a3 = Ws[ty * 4 + 3][kk];
            #pragma unroll
            for (int j = 0; j < 4; j++) {
                acc[0][j] = fmaf(a0, bb[j], acc[0][j]);
                acc[1][j] = fmaf(a1, bb[j], acc[1][j]);
                acc[2][j] = fmaf(a2, bb[j], acc[2][j]);
                acc[3][j] = fmaf(a3, bb[j], acc[3][j]);
            }
        }
        __syncthreads();
    }
    #pragma unroll
    for (int i = 0; i < 4; i++) {
        size_t roff = ((size_t)(b * T_ + qt + ty * 4 + i)) * C_ + h * HS_ + tx * 4;
        *(float4*)(att + roff) = *(float4*)(acc[i]);
    }
}

// ---------------- loss ----------------
__global__ void zero_acc_kernel(float* acc) { *acc = 0.f; }

__global__ void __launch_bounds__(256) loss_kernel(
    const float* __restrict__ logits, const int* __restrict__ targets, float* __restrict__ acc)
{
    __shared__ float red[256];
    int row = blockIdx.x;
    const float* lr = logits + (size_t)row * V_;
    int t = threadIdx.x;
    float mx = -INFINITY;
    for (int c = t; c < V_; c += 256) mx = fmaxf(mx, lr[c]);
    red[t] = mx; __syncthreads();
    for (int o = 128; o > 0; o >>= 1) { if (t < o) red[t] = fmaxf(red[t], red[t + o]); __syncthreads(); }
    float Mx = red[0]; __syncthreads();
    float s = 0.f;
    for (int c = t; c < V_; c += 256) s += __expf(lr[c] - Mx);
    red[t] = s; __syncthreads();
    for (int o = 128; o > 0; o >>= 1) { if (t < o) red[t] += red[t + o]; __syncthreads(); }
    if (t == 0) {
        float lse = logf(red[0]) + Mx;
        int tgt = targets[row];
        atomicAdd(acc, (lse - lr[tgt]) * (1.f / M_));
    }
}

__global__ void write_loss_kernel(const float* acc, float* out) { out[0] = *acc; }

// ---------------- launch ----------------
extern "C" void kernel_launch(void* const* d_in, const int* in_sizes, int n_in,
                              void* d_out, int out_size)
{
    const int*   idx   = (const int*)d_in[0];
    const int*   tgt   = (const int*)d_in[1];
    const float* tok   = (const float*)d_in[2];
    const float* pos   = (const float*)d_in[3];
    const float* ln1g  = (const float*)d_in[4];
    const float* ln1b  = (const float*)d_in[5];
    const float* Wq    = (const float*)d_in[6];
    const float* Wk    = (const float*)d_in[7];
    const float* Wv    = (const float*)d_in[8];
    const float* Wo    = (const float*)d_in[9];
    const float* bo    = (const float*)d_in[10];
    const float* ln2g  = (const float*)d_in[11];
    const float* ln2b  = (const float*)d_in[12];
    const float* W1    = (const float*)d_in[13];
    const float* b1    = (const float*)d_in[14];
    const float* W2    = (const float*)d_in[15];
    const float* b2    = (const float*)d_in[16];
    const float* lnfg  = (const float*)d_in[17];
    const float* lnfb  = (const float*)d_in[18];
    const float* Wlm   = (const float*)d_in[19];
    const float* blm   = (const float*)d_in[20];

    float *xb, *hb, *qb, *kb, *vb, *ab, *mb, *wb, *accp;
    cudaGetSymbolAddress((void**)&xb, g_x);
    cudaGetSymbolAddress((void**)&hb, g_h);
    cudaGetSymbolAddress((void**)&qb, g_q);
    cudaGetSymbolAddress((void**)&kb, g_k);
    cudaGetSymbolAddress((void**)&vb, g_v);
    cudaGetSymbolAddress((void**)&ab, g_att);
    cudaGetSymbolAddress((void**)&mb, g_mlp);
    cudaGetSymbolAddress((void**)&wb, g_wei);
    cudaGetSymbolAddress((void**)&accp, g_loss_acc);

    embed_kernel<<<M_, 256>>>(idx, tok, pos, xb);

    dim3 gC(C_ / 128, M_ / 128);          // N=1024
    dim3 gF(4 * C_ / 128, M_ / 128);      // N=4096
    dim3 gScore(T_ / 64, T_ / 64, B_ * H_);
    dim3 gAV(T_ / 64, B_ * H_);

    for (int l = 0; l < L_; l++) {
        ln_kernel<<<M_, 256>>>(xb, ln1g + (size_t)l * C_, ln1b + (size_t)l * C_, hb);
        gemm_kernel<<<gC, 256>>>(hb, Wq + (size_t)l * C_ * C_, nullptr, nullptr, qb, M_, C_, C_, 0);
        gemm_kernel<<<gC, 256>>>(hb, Wk + (size_t)l * C_ * C_, nullptr, nullptr, kb, M_, C_, C_, 0);
        gemm_kernel<<<gC, 256>>>(hb, Wv + (size_t)l * C_ * C_, nullptr, nullptr, vb, M_, C_, C_, 0);
        attn_scores_kernel<<<gScore, 256>>>(qb, kb, wb);
        softmax_kernel<<<B_ * H_ * T_, 256>>>(wb);
        attn_av_kernel<<<gAV, 256>>>(wb, vb, ab);
        gemm_kernel<<<gC, 256>>>(ab, Wo + (size_t)l * C_ * C_, bo + (size_t)l * C_, xb, xb, M_, C_, C_, 0);
        ln_kernel<<<M_, 256>>>(xb, ln2g + (size_t)l * C_, ln2b + (size_t)l * C_, hb);
        gemm_kernel<<<gF, 256>>>(hb, W1 + (size_t)l * C_ * 4 * C_, b1 + (size_t)l * 4 * C_, nullptr, mb, M_, 4 * C_, C_, 1);
        gemm_kernel<<<gC, 256>>>(mb, W2 + (size_t)l * 4 * C_ * C_, b2 + (size_t)l * C_, xb, xb, M_, C_, 4 * C_, 0);
    }

    ln_kernel<<<M_, 256>>>(xb, lnfg, lnfb, hb);

    float* out = (float*)d_out;
    dim3 gLM(V_ / 128, M_ / 128);         // 393 x 32
    gemm_kernel<<<gLM, 256>>>(hb, Wlm, blm, nullptr, out, M_, V_, C_, 0);

    if ((size_t)out_size > NLOGITS) {
        zero_acc_kernel<<<1, 1>>>(accp);
        loss_kernel<<<M_, 256>>>(out, tgt, accp);
        write_loss_kernel<<<1, 1>>>(accp, out + NLOGITS);
    }
}

// round 3
// speedup vs baseline: 2.2661x; 2.2661x over previous
#include <cuda_runtime.h>
#include <cuda_bf16.h>
#include <math.h>
#include <stdint.h>

#define B_ 4
#define T_ 1024
#define C_ 1024
#define H_ 16
#define HS_ 64
#define L_ 12
#define V_ 50304
#define M_ 4096  // B*T

static const size_t NLOGITS = (size_t)M_ * V_;

// ---------------- scratch (device globals; no allocs allowed) ----------------
__device__ float g_x[(size_t)M_ * C_];
__device__ float g_q[(size_t)M_ * C_];
__device__ float g_k[(size_t)M_ * C_];
__device__ float g_v[(size_t)M_ * C_];
__device__ float g_wei[(size_t)B_ * H_ * T_ * T_];
__device__ float g_loss_acc;

__device__ __nv_bfloat16 g_h_hi[(size_t)M_ * C_];
__device__ __nv_bfloat16 g_h_lo[(size_t)M_ * C_];
__device__ __nv_bfloat16 g_att_hi[(size_t)M_ * C_];
__device__ __nv_bfloat16 g_att_lo[(size_t)M_ * C_];
__device__ __nv_bfloat16 g_mlp_hi[(size_t)M_ * 4 * C_];
__device__ __nv_bfloat16 g_mlp_lo[(size_t)M_ * 4 * C_];
__device__ __nv_bfloat16 g_wT_hi[(size_t)V_ * C_];
__device__ __nv_bfloat16 g_wT_lo[(size_t)V_ * C_];

// ---------------- helpers ----------------
__device__ __forceinline__ uint32_t smem_u32(const void* p) {
    uint32_t a;
    asm("{ .reg .u64 t; cvta.to.shared.u64 t, %1; cvt.u32.u64 %0, t; }" : "=r"(a) : "l"(p));
    return a;
}
#define CP16(dst, src) asm volatile("cp.async.cg.shared.global [%0], [%1], 16;" :: "r"(dst), "l"(src) : "memory")
#define CP_COMMIT() asm volatile("cp.async.commit_group;" ::: "memory")
#define CP_WAIT(n)  asm volatile("cp.async.wait_group %0;" :: "n"(n) : "memory")

__device__ __forceinline__ void split_bf16(float x, __nv_bfloat16& h, __nv_bfloat16& l) {
    h = __float2bfloat16_rn(x);
    l = __float2bfloat16_rn(x - __bfloat162float(h));
}

__device__ __forceinline__ void mma_bf16(float* c, const uint32_t* a, const uint32_t* b) {
    asm volatile(
        "mma.sync.aligned.m16n8k16.row.col.f32.bf16.bf16.f32 "
        "{%0,%1,%2,%3}, {%4,%5,%6,%7}, {%8,%9}, {%0,%1,%2,%3};"
        : "+f"(c[0]), "+f"(c[1]), "+f"(c[2]), "+f"(c[3])
        : "r"(a[0]), "r"(a[1]), "r"(a[2]), "r"(a[3]), "r"(b[0]), "r"(b[1]));
}

// ---------------- weight convert + transpose: W[K][N] -> wT_hi/lo[N][K] ----------------
__global__ void __launch_bounds__(256) convw_kernel(
    const float* __restrict__ W, __nv_bfloat16* __restrict__ hiT,
    __nv_bfloat16* __restrict__ loT, int K, int N)
{
    __shared__ float tile[32][33];
    int nt = blockIdx.x * 32, kt = blockIdx.y * 32;
    int tx = threadIdx.x & 31, ty = threadIdx.x >> 5;  // 32 x 8
    #pragma unroll
    for (int j = 0; j < 4; j++) {
        int kk = ty + j * 8;
        tile[kk][tx] = W[(size_t)(kt + kk) * N + nt + tx];
    }
    __syncthreads();
    #pragma unroll
    for (int j = 0; j < 4; j++) {
        int nn = ty + j * 8;
        float v = tile[tx][nn];
        __nv_bfloat16 h, l;
        split_bf16(v, h, l);
        size_t off = (size_t)(nt + nn) * K + kt + tx;
        hiT[off] = h;
        loT[off] = l;
    }
}

// ---------------- bf16-split GEMM via mma.sync ----------------
// C = A(MxK) @ B(KxN); A given as hi/lo [M][K] bf16; B given as hi/lo transposed [N][K].
// 3 passes: Ahi*Bhi + Ahi*Blo + Alo*Bhi (fp32 accum).
// BM=128 BN=128 BK=32, 256 thr (8 warps 2x4), 3-stage cp.async pipeline.
#define GSTAGE 40960            // 4 arrays * 128 rows * 80B
#define GSMEM  (3 * GSTAGE)     // 122880
__global__ void __launch_bounds__(256) gemm_mma_kernel(
    const __nv_bfloat16* __restrict__ Ahi, const __nv_bfloat16* __restrict__ Alo,
    const __nv_bfloat16* __restrict__ Bhi, const __nv_bfloat16* __restrict__ Blo,
    const float* __restrict__ bias, const float* __restrict__ res,
    float* __restrict__ Cout, __nv_bfloat16* __restrict__ Ohi, __nv_bfloat16* __restrict__ Olo,
    int M, int N, int K, int relu)
{
    extern __shared__ char sm[];
    const uint32_t sbase = smem_u32(sm);
    const int tid = threadIdx.x;
    const int lane = tid & 31, wid = tid >> 5;
    const int wm = wid >> 2, wn = wid & 3;
    const int g = lane >> 2, tig = lane & 3;
    const int bm = blockIdx.y << 7, bn = blockIdx.x << 7;

    float acc[4][4][4];
    #pragma unroll
    for (int a = 0; a < 4; a++)
        #pragma unroll
        for (int b = 0; b < 4; b++)
            #pragma unroll
            for (int c = 0; c < 4; c++) acc[a][b][c] = 0.f;

    const int nIter = K >> 5;

    auto stage = [&](int it) {
        const uint32_t s0 = sbase + (uint32_t)(it % 3) * GSTAGE;
        const int k0 = it << 5;
        #pragma unroll
        for (int j = 0; j < 2; j++) {
            int c = tid + j * 256;           // 0..511 chunk id
            int row = c >> 2, q = c & 3;
            uint32_t d = (uint32_t)(row * 80 + q * 16);
            size_t ga = (size_t)(bm + row) * K + k0 + q * 8;
            size_t gb = (size_t)(bn + row) * K + k0 + q * 8;
            CP16(s0 + d,         Ahi + ga);
            CP16(s0 + 10240 + d, Alo + ga);
            CP16(s0 + 20480 + d, Bhi + gb);
            CP16(s0 + 30720 + d, Blo + gb);
        }
    };

    stage(0); CP_COMMIT();
    stage(1); CP_COMMIT();
    stage(2); CP_COMMIT();

    for (int i = 0; i < nIter; i++) {
        int rem = nIter - 1 - i;
        if (rem >= 2) { CP_WAIT(2); } else if (rem == 1) { CP_WAIT(1); } else { CP_WAIT(0); }
        __syncthreads();

        const char* buf = sm + (size_t)(i % 3) * GSTAGE;
        const __nv_bfloat16* Ah = (const __nv_bfloat16*)(buf);
        const __nv_bfloat16* Al = (const __nv_bfloat16*)(buf + 10240);
        const __nv_bfloat16* Bh = (const __nv_bfloat16*)(buf + 20480);
        const __nv_bfloat16* Bl = (const __nv_bfloat16*)(buf + 30720);

        #pragma unroll
        for (int ks = 0; ks < 2; ks++) {
            const int kb = ks * 16 + 2 * tig;
            uint32_t ah[4][4], al[4][4], bh[4][2], bl[4][2];
            #pragma unroll
            for (int mf = 0; mf < 4; mf++) {
                int rb = wm * 64 + mf * 16;
                ah[mf][0] = *(const uint32_t*)(Ah + (rb + g) * 40 + kb);
                ah[mf][1] = *(const uint32_t*)(Ah + (rb + g + 8) * 40 + kb);
                ah[mf][2] = *(const uint32_t*)(Ah + (rb + g) * 40 + kb + 8);
                ah[mf][3] = *(const uint32_t*)(Ah + (rb + g + 8) * 40 + kb + 8);
                al[mf][0] = *(const uint32_t*)(Al + (rb + g) * 40 + kb);
                al[mf][1] = *(const uint32_t*)(Al + (rb + g + 8) * 40 + kb);
                al[mf][2] = *(const uint32_t*)(Al + (rb + g) * 40 + kb + 8);
                al[mf][3] = *(const uint32_t*)(Al + (rb + g + 8) * 40 + kb + 8);
            }
            #pragma unroll
            for (int nf = 0; nf < 4; nf++) {
                int nb2 = wn * 32 + nf * 8;
                bh[nf][0] = *(const uint32_t*)(Bh + (nb2 + g) * 40 + kb);
                bh[nf][1] = *(const uint32_t*)(Bh + (nb2 + g) * 40 + kb + 8);
                bl[nf][0] = *(const uint32_t*)(Bl + (nb2 + g) * 40 + kb);
                bl[nf][1] = *(const uint32_t*)(Bl + (nb2 + g) * 40 + kb + 8);
            }
            #pragma unroll
            for (int mf = 0; mf < 4; mf++)
                #pragma unroll
                for (int nf = 0; nf < 4; nf++) {
                    mma_bf16(acc[mf][nf], ah[mf], bh[nf]);
                    mma_bf16(acc[mf][nf], ah[mf], bl[nf]);
                    mma_bf16(acc[mf][nf], al[mf], bh[nf]);
                }
        }
        __syncthreads();
        if (i + 3 < nIter) { stage(i + 3); CP_COMMIT(); }
    }

    // epilogue
    #pragma unroll
    for (int nf = 0; nf < 4; nf++) {
        int col = bn + wn * 32 + nf * 8 + 2 * tig;
        float2 bz = make_float2(0.f, 0.f);
        if (bias) bz = *(const float2*)(bias + col);
        #pragma unroll
        for (int mf = 0; mf < 4; mf++) {
            int row0 = bm + wm * 64 + mf * 16 + g;
            int row1 = row0 + 8;
            float c0 = acc[mf][nf][0] + bz.x;
            float c1 = acc[mf][nf][1] + bz.y;
            float c2 = acc[mf][nf][2] + bz.x;
            float c3 = acc[mf][nf][3] + bz.y;
            if (res) {
                float2 r0 = *(const float2*)(res + (size_t)row0 * N + col);
                float2 r1 = *(const float2*)(res + (size_t)row1 * N + col);
                c0 += r0.x; c1 += r0.y; c2 += r1.x; c3 += r1.y;
            }
            if (relu) {
                c0 = fmaxf(c0, 0.f); c1 = fmaxf(c1, 0.f);
                c2 = fmaxf(c2, 0.f); c3 = fmaxf(c3, 0.f);
            }
            if (Cout) {
                *(float2*)(Cout + (size_t)row0 * N + col) = make_float2(c0, c1);
                *(float2*)(Cout + (size_t)row1 * N + col) = make_float2(c2, c3);
            }
            if (Ohi) {
                __nv_bfloat16 h0, l0, h1, l1, h2, l2, h3, l3;
                split_bf16(c0, h0, l0); split_bf16(c1, h1, l1);
                split_bf16(c2, h2, l2); split_bf16(c3, h3, l3);
                *(__nv_bfloat162*)(Ohi + (size_t)row0 * N + col) = __halves2bfloat162(h0, h1);
                *(__nv_bfloat162*)(Olo + (size_t)row0 * N + col) = __halves2bfloat162(l0, l1);
                *(__nv_bfloat162*)(Ohi + (size_t)row1 * N + col) = __halves2bfloat162(h2, h3);
                *(__nv_bfloat162*)(Olo + (size_t)row1 * N + col) = __halves2bfloat162(l2, l3);
            }
        }
    }
}

// ---------------- embedding ----------------
__global__ void __launch_bounds__(256) embed_kernel(
    const int* __restrict__ idx, const float* __restrict__ tok,
    const float* __restrict__ pos, float* __restrict__ x)
{
    int row = blockIdx.x;
    int t = row & (T_ - 1);
    int token = idx[row];
    int c = threadIdx.x * 4;
    float4 a = *(const float4*)(tok + (size_t)token * C_ + c);
    float4 p = *(const float4*)(pos + (size_t)t * C_ + c);
    *(float4*)(x + (size_t)row * C_ + c) = make_float4(a.x + p.x, a.y + p.y, a.z + p.z, a.w + p.w);
}

// ---------------- layernorm -> bf16 hi/lo ----------------
__global__ void __launch_bounds__(256) ln_kernel(
    const float* __restrict__ x, const float* __restrict__ g,
    const float* __restrict__ b, __nv_bfloat16* __restrict__ yhi,
    __nv_bfloat16* __restrict__ ylo)
{
    __shared__ float red[256];
    int row = blockIdx.x;
    int t = threadIdx.x;
    const float* xr = x + (size_t)row * C_;
    float4 v = *(const float4*)(xr + t * 4);
    red[t] = v.x + v.y + v.z + v.w;
    __syncthreads();
    for (int o = 128; o > 0; o >>= 1) { if (t < o) red[t] += red[t + o]; __syncthreads(); }
    float mean = red[0] * (1.f / C_);
    __syncthreads();
    float dx = v.x - mean, dy = v.y - mean, dz = v.z - mean, dw = v.w - mean;
    red[t] = dx * dx + dy * dy + dz * dz + dw * dw;
    __syncthreads();
    for (int o = 128; o > 0; o >>= 1) { if (t < o) red[t] += red[t + o]; __syncthreads(); }
    float inv = rsqrtf(red[0] * (1.f / C_) + 1e-5f);
    float4 gv = *(const float4*)(g + t * 4);
    float4 bv = *(const float4*)(b + t * 4);
    float o0 = dx * inv * gv.x + bv.x;
    float o1 = dy * inv * gv.y + bv.y;
    float o2 = dz * inv * gv.z + bv.z;
    float o3 = dw * inv * gv.w + bv.w;
    __nv_bfloat16 h0, l0, h1, l1, h2, l2, h3, l3;
    split_bf16(o0, h0, l0); split_bf16(o1, h1, l1);
    split_bf16(o2, h2, l2); split_bf16(o3, h3, l3);
    size_t off = (size_t)row * C_ + t * 4;
    *(__nv_bfloat162*)(yhi + off)     = __halves2bfloat162(h0, h1);
    *(__nv_bfloat162*)(yhi + off + 2) = __halves2bfloat162(h2, h3);
    *(__nv_bfloat162*)(ylo + off)     = __halves2bfloat162(l0, l1);
    *(__nv_bfloat162*)(ylo + off + 2) = __halves2bfloat162(l2, l3);
}

// ---------------- attention scores ----------------
__global__ void __launch_bounds__(256) attn_scores_kernel(
    const float* __restrict__ q, const float* __restrict__ k, float* __restrict__ wei)
{
    int kt = blockIdx.x << 6;
    int qt = blockIdx.y << 6;
    if (kt > qt) return;
    int bh = blockIdx.z;
    int b = bh >> 4, h = bh & 15;
    __shared__ float Qs[64][68];
    __shared__ float Ks[64][68];
    int tid = threadIdx.x;
    const float* qbase = q + ((size_t)(b * T_ + qt)) * C_ + h * HS_;
    const float* kbase = k + ((size_t)(b * T_ + kt)) * C_ + h * HS_;
    #pragma unroll
    for (int l = tid; l < 1024; l += 256) {
        int r = l >> 4, c4 = l & 15;
        float4 v = *(const float4*)(qbase + (size_t)r * C_ + c4 * 4);
        Qs[c4 * 4 + 0][r] = v.x; Qs[c4 * 4 + 1][r] = v.y;
        Qs[c4 * 4 + 2][r] = v.z; Qs[c4 * 4 + 3][r] = v.w;
        float4 w = *(const float4*)(kbase + (size_t)r * C_ + c4 * 4);
        Ks[c4 * 4 + 0][r] = w.x; Ks[c4 * 4 + 1][r] = w.y;
        Ks[c4 * 4 + 2][r] = w.z; Ks[c4 * 4 + 3][r] = w.w;
    }
    __syncthreads();
    int tx = tid & 15, ty = tid >> 4;
    float acc[4][4];
    #pragma unroll
    for (int i = 0; i < 4; i++)
        #pragma unroll
        for (int j = 0; j < 4; j++) acc[i][j] = 0.f;
    #pragma unroll 8
    for (int d = 0; d < 64; d++) {
        float a[4], bb[4];
        *(float4*)a  = *(const float4*)(&Qs[d][ty * 4]);
        *(float4*)bb = *(const float4*)(&Ks[d][tx * 4]);
        #pragma unroll
        for (int i = 0; i < 4; i++)
            #pragma unroll
            for (int j = 0; j < 4; j++)
                acc[i][j] = fmaf(a[i], bb[j], acc[i][j]);
    }
    #pragma unroll
    for (int i = 0; i < 4; i++) {
        size_t roff = ((size_t)bh * T_ + qt + ty * 4 + i) * T_ + kt + tx * 4;
        *(float4*)(wei + roff) = *(float4*)(acc[i]);
    }
}

// ---------------- masked softmax ----------------
__global__ void __launch_bounds__(256) softmax_kernel(float* __restrict__ wei)
{
    __shared__ float red[256];
    int row = blockIdx.x;
    int q = row & (T_ - 1);
    float* w = wei + (size_t)row * T_;
    int kend = ((q >> 6) + 1) << 6;
    int t = threadIdx.x;
    int k0 = t * 4;
    float vals[4];
    float mx = -INFINITY;
    #pragma unroll
    for (int j = 0; j < 4; j++) {
        int kk = k0 + j;
        float v = (kk <= q) ? w[kk] * 0.125f : -INFINITY;
        vals[j] = v;
        mx = fmaxf(mx, v);
    }
    red[t] = mx; __syncthreads();
    for (int o = 128; o > 0; o >>= 1) { if (t < o) red[t] = fmaxf(red[t], red[t + o]); __syncthreads(); }
    float Mx = red[0]; __syncthreads();
    float s = 0.f;
    #pragma unroll
    for (int j = 0; j < 4; j++) {
        int kk = k0 + j;
        float e = (kk <= q) ? __expf(vals[j] - Mx) : 0.f;
        vals[j] = e;
        s += e;
    }
    red[t] = s; __syncthreads();
    for (int o = 128; o > 0; o >>= 1) { if (t < o) red[t] += red[t + o]; __syncthreads(); }
    float invS = 1.f / red[0];
    #pragma unroll
    for (int j = 0; j < 4; j++) {
        int kk = k0 + j;
        if (kk < kend) w[kk] = vals[j] * invS;
    }
}

// ---------------- att = wei @ V -> bf16 hi/lo ----------------
__global__ void __launch_bounds__(256) attn_av_kernel(
    const float* __restrict__ wei, const float* __restrict__ v,
    __nv_bfloat16* __restrict__ atthi, __nv_bfloat16* __restrict__ attlo)
{
    int qt = blockIdx.x << 6;
    int bh = blockIdx.y;
    int b = bh >> 4, h = bh & 15;
    __shared__ float Ws[64][68];
    __shared__ float Vs[64][68];
    int tid = threadIdx.x;
    int tx = tid & 15, ty = tid >> 4;
    float acc[4][4];
    #pragma unroll
    for (int i = 0; i < 4; i++)
        #pragma unroll
        for (int j = 0; j < 4; j++) acc[i][j] = 0.f;

    for (int kt = 0; kt <= qt; kt += 64) {
        const float* wbase = wei + ((size_t)bh * T_ + qt) * T_ + kt;
        const float* vbase = v + ((size_t)(b * T_ + kt)) * C_ + h * HS_;
        #pragma unroll
        for (int l = tid; l < 1024; l += 256) {
            int r = l >> 4, c4 = l & 15;
            *(float4*)(&Ws[r][c4 * 4]) = *(const float4*)(wbase + (size_t)r * T_ + c4 * 4);
            *(float4*)(&Vs[r][c4 * 4]) = *(const float4*)(vbase + (size_t)r * C_ + c4 * 4);
        }
        __syncthreads();
        #pragma unroll 8
        for (int kk = 0; kk < 64; kk++) {
            float bb[4];
            *(float4*)bb = *(const float4*)(&Vs[kk][tx * 4]);
            float a0 = Ws[ty * 4 + 0][kk];
            float a1 = Ws[ty * 4 + 1][kk];
            float a2 = Ws[ty * 4 + 2][kk];
            float a3 = Ws[ty * 4 + 3][kk];
            #pragma unroll
            for (int j = 0; j < 4; j++) {
                acc[0][j] = fmaf(a0, bb[j], acc[0][j]);
                acc[1][j] = fmaf(a1, bb[j], acc[1][j]);
                acc[2][j] = fmaf(a2, bb[j], acc[2][j]);
                acc[3][j] = fmaf(a3, bb[j], acc[3][j]);
            }
        }
        __syncthreads();
    }
    #pragma unroll
    for (int i = 0; i < 4; i++) {
        size_t roff = ((size_t)(b * T_ + qt + ty * 4 + i)) * C_ + h * HS_ + tx * 4;
        __nv_bfloat16 h0, l0, h1, l1, h2, l2, h3, l3;
        split_bf16(acc[i][0], h0, l0); split_bf16(acc[i][1], h1, l1);
        split_bf16(acc[i][2], h2, l2); split_bf16(acc[i][3], h3, l3);
        *(__nv_bfloat162*)(atthi + roff)     = __halves2bfloat162(h0, h1);
        *(__nv_bfloat162*)(atthi + roff + 2) = __halves2bfloat162(h2, h3);
        *(__nv_bfloat162*)(attlo + roff)     = __halves2bfloat162(l0, l1);
        *(__nv_bfloat162*)(attlo + roff + 2) = __halves2bfloat162(l2, l3);
    }
}

// ---------------- loss ----------------
__global__ void zero_acc_kernel(float* acc) { *acc = 0.f; }

__global__ void __launch_bounds__(256) loss_kernel(
    const float* __restrict__ logits, const int* __restrict__ targets, float* __restrict__ acc)
{
    __shared__ float red[256];
    int row = blockIdx.x;
    const float* lr = logits + (size_t)row * V_;
    int t = threadIdx.x;
    float mx = -INFINITY;
    for (int c = t; c < V_; c += 256) mx = fmaxf(mx, lr[c]);
    red[t] = mx; __syncthreads();
    for (int o = 128; o > 0; o >>= 1) { if (t < o) red[t] = fmaxf(red[t], red[t + o]); __syncthreads(); }
    float Mx = red[0]; __syncthreads();
    float s = 0.f;
    for (int c = t; c < V_; c += 256) s += __expf(lr[c] - Mx);
    red[t] = s; __syncthreads();
    for (int o = 128; o > 0; o >>= 1) { if (t < o) red[t] += red[t + o]; __syncthreads(); }
    if (t == 0) {
        float lse = logf(red[0]) + Mx;
        int tgt = targets[row];
        atomicAdd(acc, (lse - lr[tgt]) * (1.f / M_));
    }
}

__global__ void write_loss_kernel(const float* acc, float* out) { out[0] = *acc; }

// ---------------- launch ----------------
extern "C" void kernel_launch(void* const* d_in, const int* in_sizes, int n_in,
                              void* d_out, int out_size)
{
    const int*   idx   = (const int*)d_in[0];
    const int*   tgt   = (const int*)d_in[1];
    const float* tok   = (const float*)d_in[2];
    const float* pos   = (const float*)d_in[3];
    const float* ln1g  = (const float*)d_in[4];
    const float* ln1b  = (const float*)d_in[5];
    const float* Wq    = (const float*)d_in[6];
    const float* Wk    = (const float*)d_in[7];
    const float* Wv    = (const float*)d_in[8];
    const float* Wo    = (const float*)d_in[9];
    const float* bo    = (const float*)d_in[10];
    const float* ln2g  = (const float*)d_in[11];
    const float* ln2b  = (const float*)d_in[12];
    const float* W1    = (const float*)d_in[13];
    const float* b1    = (const float*)d_in[14];
    const float* W2    = (const float*)d_in[15];
    const float* b2    = (const float*)d_in[16];
    const float* lnfg  = (const float*)d_in[17];
    const float* lnfb  = (const float*)d_in[18];
    const float* Wlm   = (const float*)d_in[19];
    const float* blm   = (const float*)d_in[20];

    float *xb, *qb, *kb, *vb, *wb, *accp;
    __nv_bfloat16 *hh, *hl, *ah, *al, *mh, *ml, *wth, *wtl;
    cudaGetSymbolAddress((void**)&xb, g_x);
    cudaGetSymbolAddress((void**)&qb, g_q);
    cudaGetSymbolAddress((void**)&kb, g_k);
    cudaGetSymbolAddress((void**)&vb, g_v);
    cudaGetSymbolAddress((void**)&wb, g_wei);
    cudaGetSymbolAddress((void**)&accp, g_loss_acc);
    cudaGetSymbolAddress((void**)&hh, g_h_hi);
    cudaGetSymbolAddress((void**)&hl, g_h_lo);
    cudaGetSymbolAddress((void**)&ah, g_att_hi);
    cudaGetSymbolAddress((void**)&al, g_att_lo);
    cudaGetSymbolAddress((void**)&mh, g_mlp_hi);
    cudaGetSymbolAddress((void**)&ml, g_mlp_lo);
    cudaGetSymbolAddress((void**)&wth, g_wT_hi);
    cudaGetSymbolAddress((void**)&wtl, g_wT_lo);

    cudaFuncSetAttribute(gemm_mma_kernel, cudaFuncAttributeMaxDynamicSharedMemorySize, GSMEM);

    embed_kernel<<<M_, 256>>>(idx, tok, pos, xb);

    dim3 gC(C_ / 128, M_ / 128);
    dim3 gF(4 * C_ / 128, M_ / 128);
    dim3 gScore(T_ / 64, T_ / 64, B_ * H_);
    dim3 gAV(T_ / 64, B_ * H_);
    dim3 cvC(C_ / 32, C_ / 32);            // W: C x C
    dim3 cv1(4 * C_ / 32, C_ / 32);        // W1: K=C, N=4C
    dim3 cv2(C_ / 32, 4 * C_ / 32);        // W2: K=4C, N=C
    dim3 cvLM(V_ / 32, C_ / 32);           // Wlm: K=C, N=V

    for (int l = 0; l < L_; l++) {
        ln_kernel<<<M_, 256>>>(xb, ln1g + (size_t)l * C_, ln1b + (size_t)l * C_, hh, hl);

        convw_kernel<<<cvC, 256>>>(Wq + (size_t)l * C_ * C_, wth, wtl, C_, C_);
        gemm_mma_kernel<<<gC, 256, GSMEM>>>(hh, hl, wth, wtl, nullptr, nullptr, qb, nullptr, nullptr, M_, C_, C_, 0);
        convw_kernel<<<cvC, 256>>>(Wk + (size_t)l * C_ * C_, wth, wtl, C_, C_);
        gemm_mma_kernel<<<gC, 256, GSMEM>>>(hh, hl, wth, wtl, nullptr, nullptr, kb, nullptr, nullptr, M_, C_, C_, 0);
        convw_kernel<<<cvC, 256>>>(Wv + (size_t)l * C_ * C_, wth, wtl, C_, C_);
        gemm_mma_kernel<<<gC, 256, GSMEM>>>(hh, hl, wth, wtl, nullptr, nullptr, vb, nullptr, nullptr, M_, C_, C_, 0);

        attn_scores_kernel<<<gScore, 256>>>(qb, kb, wb);
        softmax_kernel<<<B_ * H_ * T_, 256>>>(wb);
        attn_av_kernel<<<gAV, 256>>>(wb, vb, ah, al);

        convw_kernel<<<cvC, 256>>>(Wo + (size_t)l * C_ * C_, wth, wtl, C_, C_);
        gemm_mma_kernel<<<gC, 256, GSMEM>>>(ah, al, wth, wtl, bo + (size_t)l * C_, xb, xb, nullptr, nullptr, M_, C_, C_, 0);

        ln_kernel<<<M_, 256>>>(xb, ln2g + (size_t)l * C_, ln2b + (size_t)l * C_, hh, hl);

        convw_kernel<<<cv1, 256>>>(W1 + (size_t)l * C_ * 4 * C_, wth, wtl, C_, 4 * C_);
        gemm_mma_kernel<<<gF, 256, GSMEM>>>(hh, hl, wth, wtl, b1 + (size_t)l * 4 * C_, nullptr, nullptr, mh, ml, M_, 4 * C_, C_, 1);
        convw_kernel<<<cv2, 256>>>(W2 + (size_t)l * 4 * C_ * C_, wth, wtl, 4 * C_, C_);
        gemm_mma_kernel<<<gC, 256, GSMEM>>>(mh, ml, wth, wtl, b2 + (size_t)l * C_, xb, xb, nullptr, nullptr, M_, C_, 4 * C_, 0);
    }

    ln_kernel<<<M_, 256>>>(xb, lnfg, lnfb, hh, hl);

    float* out = (float*)d_out;
    convw_kernel<<<cvLM, 256>>>(Wlm, wth, wtl, C_, V_);
    dim3 gLM(V_ / 128, M_ / 128);
    gemm_mma_kernel<<<gLM, 256, GSMEM>>>(hh, hl, wth, wtl, blm, nullptr, out, nullptr, nullptr, M_, V_, C_, 0);

    if ((size_t)out_size > NLOGITS) {
        zero_acc_kernel<<<1, 1>>>(accp);
        loss_kernel<<<M_, 256>>>(out, tgt, accp);
        write_loss_kernel<<<1, 1>>>(accp, out + NLOGITS);
    }
}

// round 4
// speedup vs baseline: 2.3209x; 1.0242x over previous
#include <cuda_runtime.h>
#include <cuda_bf16.h>
#include <math.h>
#include <stdint.h>

#define B_ 4
#define T_ 1024
#define C_ 1024
#define H_ 16
#define HS_ 64
#define L_ 12
#define V_ 50304
#define M_ 4096  // B*T

static const size_t NLOGITS = (size_t)M_ * V_;

// ---------------- scratch (device globals; no allocs allowed) ----------------
__device__ float g_x[(size_t)M_ * C_];
__device__ float g_qkv[(size_t)M_ * 3 * C_];
__device__ float g_wei[(size_t)B_ * H_ * T_ * T_];
__device__ float g_loss_acc;

__device__ __nv_bfloat16 g_h_hi[(size_t)M_ * C_];
__device__ __nv_bfloat16 g_h_lo[(size_t)M_ * C_];
__device__ __nv_bfloat16 g_att_hi[(size_t)M_ * C_];
__device__ __nv_bfloat16 g_att_lo[(size_t)M_ * C_];
__device__ __nv_bfloat16 g_mlp_hi[(size_t)M_ * 4 * C_];
__device__ __nv_bfloat16 g_mlp_lo[(size_t)M_ * 4 * C_];
__device__ __nv_bfloat16 g_wT_hi[(size_t)V_ * C_];
__device__ __nv_bfloat16 g_wT_lo[(size_t)V_ * C_];

// ---------------- helpers ----------------
__device__ __forceinline__ uint32_t smem_u32(const void* p) {
    uint32_t a;
    asm("{ .reg .u64 t; cvta.to.shared.u64 t, %1; cvt.u32.u64 %0, t; }" : "=r"(a) : "l"(p));
    return a;
}
#define CP16(dst, src) asm volatile("cp.async.cg.shared.global [%0], [%1], 16;" :: "r"(dst), "l"(src) : "memory")
#define CP_COMMIT() asm volatile("cp.async.commit_group;" ::: "memory")
#define CP_WAIT(n)  asm volatile("cp.async.wait_group %0;" :: "n"(n) : "memory")

__device__ __forceinline__ void split_bf16(float x, __nv_bfloat16& h, __nv_bfloat16& l) {
    h = __float2bfloat16_rn(x);
    l = __float2bfloat16_rn(x - __bfloat162float(h));
}

__device__ __forceinline__ void mma_bf16(float* c, const uint32_t* a, const uint32_t* b) {
    asm volatile(
        "mma.sync.aligned.m16n8k16.row.col.f32.bf16.bf16.f32 "
        "{%0,%1,%2,%3}, {%4,%5,%6,%7}, {%8,%9}, {%0,%1,%2,%3};"
        : "+f"(c[0]), "+f"(c[1]), "+f"(c[2]), "+f"(c[3])
        : "r"(a[0]), "r"(a[1]), "r"(a[2]), "r"(a[3]), "r"(b[0]), "r"(b[1]));
}

__device__ __forceinline__ void ldm_x4(uint32_t* r, uint32_t addr) {
    asm volatile("ldmatrix.sync.aligned.m8n8.x4.shared.b16 {%0,%1,%2,%3}, [%4];"
        : "=r"(r[0]), "=r"(r[1]), "=r"(r[2]), "=r"(r[3]) : "r"(addr));
}

// ---------------- weight convert + transpose: W[K][N] -> wT_hi/lo[N][K] ----------------
__global__ void __launch_bounds__(256) convw_kernel(
    const float* __restrict__ W, __nv_bfloat16* __restrict__ hiT,
    __nv_bfloat16* __restrict__ loT, int K, int N)
{
    __shared__ float tile[32][33];
    int nt = blockIdx.x * 32, kt = blockIdx.y * 32;
    int tx = threadIdx.x & 31, ty = threadIdx.x >> 5;  // 32 x 8
    #pragma unroll
    for (int j = 0; j < 4; j++) {
        int kk = ty + j * 8;
        tile[kk][tx] = W[(size_t)(kt + kk) * N + nt + tx];
    }
    __syncthreads();
    #pragma unroll
    for (int j = 0; j < 4; j++) {
        int nn = ty + j * 8;
        float v = tile[tx][nn];
        __nv_bfloat16 h, l;
        split_bf16(v, h, l);
        size_t off = (size_t)(nt + nn) * K + kt + tx;
        hiT[off] = h;
        loT[off] = l;
    }
}

// ---------------- bf16-split GEMM via mma.sync + ldmatrix ----------------
// C = A(MxK) @ B(KxN); A hi/lo [M][K] bf16; B hi/lo transposed [N][K].
// 3 passes (Ahi*Bhi + Ahi*Blo + Alo*Bhi), fp32 accum.
// BM=128 BN=128 BK=32, 256 thr (8 warps 2x4), 3-stage cp.async, 1 sync/iter.
#define GSTAGE 40960            // 4 arrays * 128 rows * 80B
#define GSMEM  (3 * GSTAGE)     // 122880
__global__ void __launch_bounds__(256) gemm_mma_kernel(
    const __nv_bfloat16* __restrict__ Ahi, const __nv_bfloat16* __restrict__ Alo,
    const __nv_bfloat16* __restrict__ Bhi, const __nv_bfloat16* __restrict__ Blo,
    const float* __restrict__ bias, const float* __restrict__ res,
    float* __restrict__ Cout, __nv_bfloat16* __restrict__ Ohi, __nv_bfloat16* __restrict__ Olo,
    int M, int N, int K, int relu)
{
    extern __shared__ char sm[];
    const uint32_t sbase = smem_u32(sm);
    const int tid = threadIdx.x;
    const int lane = tid & 31, wid = tid >> 5;
    const int wm = wid >> 2, wn = wid & 3;
    const int g = lane >> 2, tig = lane & 3;
    const int bm = blockIdx.y << 7, bn = blockIdx.x << 7;

    // ldmatrix lane-relative offsets
    const uint32_t aoff = (uint32_t)((wm * 64 + (lane & 15)) * 80 + (lane >> 4) * 16);
    const uint32_t boff = (uint32_t)((wn * 32 + (lane & 7) + ((lane >> 4) << 3)) * 80 + ((lane >> 3) & 1) * 16);

    float acc[4][4][4];
    #pragma unroll
    for (int a = 0; a < 4; a++)
        #pragma unroll
        for (int b = 0; b < 4; b++)
            #pragma unroll
            for (int c = 0; c < 4; c++) acc[a][b][c] = 0.f;

    const int nIter = K >> 5;

    auto stage = [&](int it) {
        const uint32_t s0 = sbase + (uint32_t)(it % 3) * GSTAGE;
        const int k0 = it << 5;
        #pragma unroll
        for (int j = 0; j < 2; j++) {
            int c = tid + j * 256;           // 0..511 chunk id
            int row = c >> 2, q = c & 3;
            uint32_t d = (uint32_t)(row * 80 + q * 16);
            size_t ga = (size_t)(bm + row) * K + k0 + q * 8;
            size_t gb = (size_t)(bn + row) * K + k0 + q * 8;
            CP16(s0 + d,         Ahi + ga);
            CP16(s0 + 10240 + d, Alo + ga);
            CP16(s0 + 20480 + d, Bhi + gb);
            CP16(s0 + 30720 + d, Blo + gb);
        }
    };

    stage(0); CP_COMMIT();
    if (nIter > 1) { stage(1); CP_COMMIT(); }

    for (int i = 0; i < nIter; i++) {
        if (i + 1 < nIter) { CP_WAIT(1); } else { CP_WAIT(0); }
        __syncthreads();
        if (i + 2 < nIter) { stage(i + 2); CP_COMMIT(); }

        const uint32_t s0 = sbase + (uint32_t)(i % 3) * GSTAGE;
        #pragma unroll
        for (int ks = 0; ks < 2; ks++) {
            const uint32_t kofs = (uint32_t)(ks * 32);
            uint32_t ah[4][4], al[4][4], bh[4][2], bl[4][2];
            #pragma unroll
            for (int mf = 0; mf < 4; mf++) {
                uint32_t ad = s0 + aoff + (uint32_t)(mf * 16 * 80) + kofs;
                ldm_x4(ah[mf], ad);
                ldm_x4(al[mf], ad + 10240);
            }
            #pragma unroll
            for (int p = 0; p < 2; p++) {
                uint32_t bd = s0 + 20480 + boff + (uint32_t)(p * 16 * 80) + kofs;
                uint32_t r[4];
                ldm_x4(r, bd);
                bh[2 * p][0] = r[0]; bh[2 * p][1] = r[1];
                bh[2 * p + 1][0] = r[2]; bh[2 * p + 1][1] = r[3];
                ldm_x4(r, bd + 10240);
                bl[2 * p][0] = r[0]; bl[2 * p][1] = r[1];
                bl[2 * p + 1][0] = r[2]; bl[2 * p + 1][1] = r[3];
            }
            // pass-major MMA order: 16 independent accumulators between reuses
            #pragma unroll
            for (int mf = 0; mf < 4; mf++)
                #pragma unroll
                for (int nf = 0; nf < 4; nf++)
                    mma_bf16(acc[mf][nf], ah[mf], bh[nf]);
            #pragma unroll
            for (int mf = 0; mf < 4; mf++)
                #pragma unroll
                for (int nf = 0; nf < 4; nf++)
                    mma_bf16(acc[mf][nf], ah[mf], bl[nf]);
            #pragma unroll
            for (int mf = 0; mf < 4; mf++)
                #pragma unroll
                for (int nf = 0; nf < 4; nf++)
                    mma_bf16(acc[mf][nf], al[mf], bh[nf]);
        }
    }

    // epilogue
    #pragma unroll
    for (int nf = 0; nf < 4; nf++) {
        int col = bn + wn * 32 + nf * 8 + 2 * tig;
        float2 bz = make_float2(0.f, 0.f);
        if (bias) bz = *(const float2*)(bias + col);
        #pragma unroll
        for (int mf = 0; mf < 4; mf++) {
            int row0 = bm + wm * 64 + mf * 16 + g;
            int row1 = row0 + 8;
            float c0 = acc[mf][nf][0] + bz.x;
            float c1 = acc[mf][nf][1] + bz.y;
            float c2 = acc[mf][nf][2] + bz.x;
            float c3 = acc[mf][nf][3] + bz.y;
            if (res) {
                float2 r0 = *(const float2*)(res + (size_t)row0 * N + col);
                float2 r1 = *(const float2*)(res + (size_t)row1 * N + col);
                c0 += r0.x; c1 += r0.y; c2 += r1.x; c3 += r1.y;
            }
            if (relu) {
                c0 = fmaxf(c0, 0.f); c1 = fmaxf(c1, 0.f);
                c2 = fmaxf(c2, 0.f); c3 = fmaxf(c3, 0.f);
            }
            if (Cout) {
                *(float2*)(Cout + (size_t)row0 * N + col) = make_float2(c0, c1);
                *(float2*)(Cout + (size_t)row1 * N + col) = make_float2(c2, c3);
            }
            if (Ohi) {
                __nv_bfloat16 h0, l0, h1, l1, h2, l2, h3, l3;
                split_bf16(c0, h0, l0); split_bf16(c1, h1, l1);
                split_bf16(c2, h2, l2); split_bf16(c3, h3, l3);
                *(__nv_bfloat162*)(Ohi + (size_t)row0 * N + col) = __halves2bfloat162(h0, h1);
                *(__nv_bfloat162*)(Olo + (size_t)row0 * N + col) = __halves2bfloat162(l0, l1);
                *(__nv_bfloat162*)(Ohi + (size_t)row1 * N + col) = __halves2bfloat162(h2, h3);
                *(__nv_bfloat162*)(Olo + (size_t)row1 * N + col) = __halves2bfloat162(l2, l3);
            }
        }
    }
}

// ---------------- embedding ----------------
__global__ void __launch_bounds__(256) embed_kernel(
    const int* __restrict__ idx, const float* __restrict__ tok,
    const float* __restrict__ pos, float* __restrict__ x)
{
    int row = blockIdx.x;
    int t = row & (T_ - 1);
    int token = idx[row];
    int c = threadIdx.x * 4;
    float4 a = *(const float4*)(tok + (size_t)token * C_ + c);
    float4 p = *(const float4*)(pos + (size_t)t * C_ + c);
    *(float4*)(x + (size_t)row * C_ + c) = make_float4(a.x + p.x, a.y + p.y, a.z + p.z, a.w + p.w);
}

// ---------------- layernorm -> bf16 hi/lo ----------------
__global__ void __launch_bounds__(256) ln_kernel(
    const float* __restrict__ x, const float* __restrict__ g,
    const float* __restrict__ b, __nv_bfloat16* __restrict__ yhi,
    __nv_bfloat16* __restrict__ ylo)
{
    __shared__ float red[256];
    int row = blockIdx.x;
    int t = threadIdx.x;
    const float* xr = x + (size_t)row * C_;
    float4 v = *(const float4*)(xr + t * 4);
    red[t] = v.x + v.y + v.z + v.w;
    __syncthreads();
    for (int o = 128; o > 0; o >>= 1) { if (t < o) red[t] += red[t + o]; __syncthreads(); }
    float mean = red[0] * (1.f / C_);
    __syncthreads();
    float dx = v.x - mean, dy = v.y - mean, dz = v.z - mean, dw = v.w - mean;
    red[t] = dx * dx + dy * dy + dz * dz + dw * dw;
    __syncthreads();
    for (int o = 128; o > 0; o >>= 1) { if (t < o) red[t] += red[t + o]; __syncthreads(); }
    float inv = rsqrtf(red[0] * (1.f / C_) + 1e-5f);
    float4 gv = *(const float4*)(g + t * 4);
    float4 bv = *(const float4*)(b + t * 4);
    float o0 = dx * inv * gv.x + bv.x;
    float o1 = dy * inv * gv.y + bv.y;
    float o2 = dz * inv * gv.z + bv.z;
    float o3 = dw * inv * gv.w + bv.w;
    __nv_bfloat16 h0, l0, h1, l1, h2, l2, h3, l3;
    split_bf16(o0, h0, l0); split_bf16(o1, h1, l1);
    split_bf16(o2, h2, l2); split_bf16(o3, h3, l3);
    size_t off = (size_t)row * C_ + t * 4;
    *(__nv_bfloat162*)(yhi + off)     = __halves2bfloat162(h0, h1);
    *(__nv_bfloat162*)(yhi + off + 2) = __halves2bfloat162(h2, h3);
    *(__nv_bfloat162*)(ylo + off)     = __halves2bfloat162(l0, l1);
    *(__nv_bfloat162*)(ylo + off + 2) = __halves2bfloat162(l2, l3);
}

// ---------------- attention scores (q,k from packed qkv[M][3C]) ----------------
__global__ void __launch_bounds__(256) attn_scores_kernel(
    const float* __restrict__ qkv, float* __restrict__ wei)
{
    int kt = blockIdx.x << 6;
    int qt = blockIdx.y << 6;
    if (kt > qt) return;
    int bh = blockIdx.z;
    int b = bh >> 4, h = bh & 15;
    __shared__ float Qs[64][68];
    __shared__ float Ks[64][68];
    int tid = threadIdx.x;
    const int RS = 3 * C_;
    const float* qbase = qkv + (size_t)(b * T_ + qt) * RS + h * HS_;
    const float* kbase = qkv + (size_t)(b * T_ + kt) * RS + C_ + h * HS_;
    #pragma unroll
    for (int l = tid; l < 1024; l += 256) {
        int r = l >> 4, c4 = l & 15;
        float4 v = *(const float4*)(qbase + (size_t)r * RS + c4 * 4);
        Qs[c4 * 4 + 0][r] = v.x; Qs[c4 * 4 + 1][r] = v.y;
        Qs[c4 * 4 + 2][r] = v.z; Qs[c4 * 4 + 3][r] = v.w;
        float4 w = *(const float4*)(kbase + (size_t)r * RS + c4 * 4);
        Ks[c4 * 4 + 0][r] = w.x; Ks[c4 * 4 + 1][r] = w.y;
        Ks[c4 * 4 + 2][r] = w.z; Ks[c4 * 4 + 3][r] = w.w;
    }
    __syncthreads();
    int tx = tid & 15, ty = tid >> 4;
    float acc[4][4];
    #pragma unroll
    for (int i = 0; i < 4; i++)
        #pragma unroll
        for (int j = 0; j < 4; j++) acc[i][j] = 0.f;
    #pragma unroll 8
    for (int d = 0; d < 64; d++) {
        float a[4], bb[4];
        *(float4*)a  = *(const float4*)(&Qs[d][ty * 4]);
        *(float4*)bb = *(const float4*)(&Ks[d][tx * 4]);
        #pragma unroll
        for (int i = 0; i < 4; i++)
            #pragma unroll
            for (int j = 0; j < 4; j++)
                acc[i][j] = fmaf(a[i], bb[j], acc[i][j]);
    }
    #pragma unroll
    for (int i = 0; i < 4; i++) {
        size_t roff = ((size_t)bh * T_ + qt + ty * 4 + i) * T_ + kt + tx * 4;
        *(float4*)(wei + roff) = *(float4*)(acc[i]);
    }
}

// ---------------- masked softmax ----------------
__global__ void __launch_bounds__(256) softmax_kernel(float* __restrict__ wei)
{
    __shared__ float red[256];
    int row = blockIdx.x;
    int q = row & (T_ - 1);
    float* w = wei + (size_t)row * T_;
    int kend = ((q >> 6) + 1) << 6;
    int t = threadIdx.x;
    int k0 = t * 4;
    float vals[4];
    float mx = -INFINITY;
    #pragma unroll
    for (int j = 0; j < 4; j++) {
        int kk = k0 + j;
        float v = (kk <= q) ? w[kk] * 0.125f : -INFINITY;
        vals[j] = v;
        mx = fmaxf(mx, v);
    }
    red[t] = mx; __syncthreads();
    for (int o = 128; o > 0; o >>= 1) { if (t < o) red[t] = fmaxf(red[t], red[t + o]); __syncthreads(); }
    float Mx = red[0]; __syncthreads();
    float s = 0.f;
    #pragma unroll
    for (int j = 0; j < 4; j++) {
        int kk = k0 + j;
        float e = (kk <= q) ? __expf(vals[j] - Mx) : 0.f;
        vals[j] = e;
        s += e;
    }
    red[t] = s; __syncthreads();
    for (int o = 128; o > 0; o >>= 1) { if (t < o) red[t] += red[t + o]; __syncthreads(); }
    float invS = 1.f / red[0];
    #pragma unroll
    for (int j = 0; j < 4; j++) {
        int kk = k0 + j;
        if (kk < kend) w[kk] = vals[j] * invS;
    }
}

// ---------------- att = wei @ V -> bf16 hi/lo ----------------
__global__ void __launch_bounds__(256) attn_av_kernel(
    const float* __restrict__ wei, const float* __restrict__ qkv,
    __nv_bfloat16* __restrict__ atthi, __nv_bfloat16* __restrict__ attlo)
{
    int qt = blockIdx.x << 6;
    int bh = blockIdx.y;
    int b = bh >> 4, h = bh & 15;
    __shared__ float Ws[64][68];
    __shared__ float Vs[64][68];
    int tid = threadIdx.x;
    int tx = tid & 15, ty = tid >> 4;
    const int RS = 3 * C_;
    float acc[4][4];
    #pragma unroll
    for (int i = 0; i < 4; i++)
        #pragma unroll
        for (int j = 0; j < 4; j++) acc[i][j] = 0.f;

    for (int kt = 0; kt <= qt; kt += 64) {
        const float* wbase = wei + ((size_t)bh * T_ + qt) * T_ + kt;
        const float* vbase = qkv + (size_t)(b * T_ + kt) * RS + 2 * C_ + h * HS_;
        #pragma unroll
        for (int l = tid; l < 1024; l += 256) {
            int r = l >> 4, c4 = l & 15;
            *(float4*)(&Ws[r][c4 * 4]) = *(const float4*)(wbase + (size_t)r * T_ + c4 * 4);
            *(float4*)(&Vs[r][c4 * 4]) = *(const float4*)(vbase + (size_t)r * RS + c4 * 4);
        }
        __syncthreads();
        #pragma unroll 8
        for (int kk = 0; kk < 64; kk++) {
            float bb[4];
            *(float4*)bb = *(const float4*)(&Vs[kk][tx * 4]);
            float a0 = Ws[ty * 4 + 0][kk];
            float a1 = Ws[ty * 4 + 1][kk];
            float a2 = Ws[ty * 4 + 2][kk];
            float a3 = Ws[ty * 4 + 3][kk];
            #pragma unroll
            for (int j = 0; j < 4; j++) {
                acc[0][j] = fmaf(a0, bb[j], acc[0][j]);
                acc[1][j] = fmaf(a1, bb[j], acc[1][j]);
                acc[2][j] = fmaf(a2, bb[j], acc[2][j]);
                acc[3][j] = fmaf(a3, bb[j], acc[3][j]);
            }
        }
        __syncthreads();
    }
    #pragma unroll
    for (int i = 0; i < 4; i++) {
        size_t roff = ((size_t)(b * T_ + qt + ty * 4 + i)) * C_ + h * HS_ + tx * 4;
        __nv_bfloat16 h0, l0, h1, l1, h2, l2, h3, l3;
        split_bf16(acc[i][0], h0, l0); split_bf16(acc[i][1], h1, l1);
        split_bf16(acc[i][2], h2, l2); split_bf16(acc[i][3], h3, l3);
        *(__nv_bfloat162*)(atthi + roff)     = __halves2bfloat162(h0, h1);
        *(__nv_bfloat162*)(atthi + roff + 2) = __halves2bfloat162(h2, h3);
        *(__nv_bfloat162*)(attlo + roff)     = __halves2bfloat162(l0, l1);
        *(__nv_bfloat162*)(attlo + roff + 2) = __halves2bfloat162(l2, l3);
    }
}

// ---------------- loss ----------------
__global__ void zero_acc_kernel(float* acc) { *acc = 0.f; }

__global__ void __launch_bounds__(256) loss_kernel(
    const float* __restrict__ logits, const int* __restrict__ targets, float* __restrict__ acc)
{
    __shared__ float red[256];
    int row = blockIdx.x;
    const float* lr = logits + (size_t)row * V_;
    int t = threadIdx.x;
    float mx = -INFINITY;
    for (int c = t; c < V_; c += 256) mx = fmaxf(mx, lr[c]);
    red[t] = mx; __syncthreads();
    for (int o = 128; o > 0; o >>= 1) { if (t < o) red[t] = fmaxf(red[t], red[t + o]); __syncthreads(); }
    float Mx = red[0]; __syncthreads();
    float s = 0.f;
    for (int c = t; c < V_; c += 256) s += __expf(lr[c] - Mx);
    red[t] = s; __syncthreads();
    for (int o = 128; o > 0; o >>= 1) { if (t < o) red[t] += red[t + o]; __syncthreads(); }
    if (t == 0) {
        float lse = logf(red[0]) + Mx;
        int tgt = targets[row];
        atomicAdd(acc, (lse - lr[tgt]) * (1.f / M_));
    }
}

__global__ void write_loss_kernel(const float* acc, float* out) { out[0] = *acc; }

// ---------------- launch ----------------
extern "C" void kernel_launch(void* const* d_in, const int* in_sizes, int n_in,
                              void* d_out, int out_size)
{
    const int*   idx   = (const int*)d_in[0];
    const int*   tgt   = (const int*)d_in[1];
    const float* tok   = (const float*)d_in[2];
    const float* pos   = (const float*)d_in[3];
    const float* ln1g  = (const float*)d_in[4];
    const float* ln1b  = (const float*)d_in[5];
    const float* Wq    = (const float*)d_in[6];
    const float* Wk    = (const float*)d_in[7];
    const float* Wv    = (const float*)d_in[8];
    const float* Wo    = (const float*)d_in[9];
    const float* bo    = (const float*)d_in[10];
    const float* ln2g  = (const float*)d_in[11];
    const float* ln2b  = (const float*)d_in[12];
    const float* W1    = (const float*)d_in[13];
    const float* b1    = (const float*)d_in[14];
    const float* W2    = (const float*)d_in[15];
    const float* b2    = (const float*)d_in[16];
    const float* lnfg  = (const float*)d_in[17];
    const float* lnfb  = (const float*)d_in[18];
    const float* Wlm   = (const float*)d_in[19];
    const float* blm   = (const float*)d_in[20];

    float *xb, *qkvb, *wb, *accp;
    __nv_bfloat16 *hh, *hl, *ah, *al, *mh, *ml, *wth, *wtl;
    cudaGetSymbolAddress((void**)&xb, g_x);
    cudaGetSymbolAddress((void**)&qkvb, g_qkv);
    cudaGetSymbolAddress((void**)&wb, g_wei);
    cudaGetSymbolAddress((void**)&accp, g_loss_acc);
    cudaGetSymbolAddress((void**)&hh, g_h_hi);
    cudaGetSymbolAddress((void**)&hl, g_h_lo);
    cudaGetSymbolAddress((void**)&ah, g_att_hi);
    cudaGetSymbolAddress((void**)&al, g_att_lo);
    cudaGetSymbolAddress((void**)&mh, g_mlp_hi);
    cudaGetSymbolAddress((void**)&ml, g_mlp_lo);
    cudaGetSymbolAddress((void**)&wth, g_wT_hi);
    cudaGetSymbolAddress((void**)&wtl, g_wT_lo);

    cudaFuncSetAttribute(gemm_mma_kernel, cudaFuncAttributeMaxDynamicSharedMemorySize, GSMEM);

    embed_kernel<<<M_, 256>>>(idx, tok, pos, xb);

    dim3 gC(C_ / 128, M_ / 128);
    dim3 gQKV(3 * C_ / 128, M_ / 128);
    dim3 gF(4 * C_ / 128, M_ / 128);
    dim3 gScore(T_ / 64, T_ / 64, B_ * H_);
    dim3 gAV(T_ / 64, B_ * H_);
    dim3 cvC(C_ / 32, C_ / 32);            // W: C x C
    dim3 cv1(4 * C_ / 32, C_ / 32);        // W1: K=C, N=4C
    dim3 cv2(C_ / 32, 4 * C_ / 32);        // W2: K=4C, N=C
    dim3 cvLM(V_ / 32, C_ / 32);           // Wlm: K=C, N=V

    for (int l = 0; l < L_; l++) {
        ln_kernel<<<M_, 256>>>(xb, ln1g + (size_t)l * C_, ln1b + (size_t)l * C_, hh, hl);

        // pack Wq|Wk|Wv transposed into wT rows [0,C),[C,2C),[2C,3C)
        convw_kernel<<<cvC, 256>>>(Wq + (size_t)l * C_ * C_, wth,                    wtl,                    C_, C_);
        convw_kernel<<<cvC, 256>>>(Wk + (size_t)l * C_ * C_, wth + (size_t)C_ * C_,  wtl + (size_t)C_ * C_,  C_, C_);
        convw_kernel<<<cvC, 256>>>(Wv + (size_t)l * C_ * C_, wth + (size_t)2 * C_ * C_, wtl + (size_t)2 * C_ * C_, C_, C_);
        gemm_mma_kernel<<<gQKV, 256, GSMEM>>>(hh, hl, wth, wtl, nullptr, nullptr, qkvb, nullptr, nullptr, M_, 3 * C_, C_, 0);

        attn_scores_kernel<<<gScore, 256>>>(qkvb, wb);
        softmax_kernel<<<B_ * H_ * T_, 256>>>(wb);
        attn_av_kernel<<<gAV, 256>>>(wb, qkvb, ah, al);

        convw_kernel<<<cvC, 256>>>(Wo + (size_t)l * C_ * C_, wth, wtl, C_, C_);
        gemm_mma_kernel<<<gC, 256, GSMEM>>>(ah, al, wth, wtl, bo + (size_t)l * C_, xb, xb, nullptr, nullptr, M_, C_, C_, 0);

        ln_kernel<<<M_, 256>>>(xb, ln2g + (size_t)l * C_, ln2b + (size_t)l * C_, hh, hl);

        convw_kernel<<<cv1, 256>>>(W1 + (size_t)l * C_ * 4 * C_, wth, wtl, C_, 4 * C_);
        gemm_mma_kernel<<<gF, 256, GSMEM>>>(hh, hl, wth, wtl, b1 + (size_t)l * 4 * C_, nullptr, nullptr, mh, ml, M_, 4 * C_, C_, 1);
        convw_kernel<<<cv2, 256>>>(W2 + (size_t)l * 4 * C_ * C_, wth, wtl, 4 * C_, C_);
        gemm_mma_kernel<<<gC, 256, GSMEM>>>(mh, ml, wth, wtl, b2 + (size_t)l * C_, xb, xb, nullptr, nullptr, M_, C_, 4 * C_, 0);
    }

    ln_kernel<<<M_, 256>>>(xb, lnfg, lnfb, hh, hl);

    float* out = (float*)d_out;
    convw_kernel<<<cvLM, 256>>>(Wlm, wth, wtl, C_, V_);
    dim3 gLM(V_ / 128, M_ / 128);
    gemm_mma_kernel<<<gLM, 256, GSMEM>>>(hh, hl, wth, wtl, blm, nullptr, out, nullptr, nullptr, M_, V_, C_, 0);

    if ((size_t)out_size > NLOGITS) {
        zero_acc_kernel<<<1, 1>>>(accp);
        loss_kernel<<<M_, 256>>>(out, tgt, accp);
        write_loss_kernel<<<1, 1>>>(accp, out + NLOGITS);
    }
}